// round 14
// baseline (speedup 1.0000x reference)
#include <cuda_runtime.h>
#include <cuda_bf16.h>
#include <math.h>
#include <stdint.h>

#define HC   128
#define NH   8
#define COLS 256
#define MAXN 50000
#define MAXM 400000
#define TM   128   // rows per tile (proj/out)
#define TE   128   // edges per tile (edge kernel)

typedef unsigned long long ull;

// Scratch (device globals — no allocation allowed)
__device__ float g_q[MAXN * HC];
__device__ float g_k[MAXN * HC];
__device__ float g_v[MAXN * HC];
__device__ float g_agg[MAXN * HC];
__device__ float g_denom[MAXN * NH];

__device__ __forceinline__ uint32_t smem_u32(const void* p) {
    uint32_t a;
    asm("{ .reg .u64 t; cvta.to.shared.u64 t, %1; cvt.u32.u64 %0, t; }"
        : "=r"(a) : "l"(p));
    return a;
}

// ---------------------------------------------------------------------------
// mma.sync / ldmatrix (base PTX ISA — valid for compute_103)
// ---------------------------------------------------------------------------
#define MMA_BF16(c, a, b) \
    asm volatile( \
        "mma.sync.aligned.m16n8k16.row.col.f32.bf16.bf16.f32 " \
        "{%0,%1,%2,%3}, {%4,%5,%6,%7}, {%8,%9}, {%0,%1,%2,%3};" \
        : "+f"((c)[0]), "+f"((c)[1]), "+f"((c)[2]), "+f"((c)[3]) \
        : "r"((a)[0]), "r"((a)[1]), "r"((a)[2]), "r"((a)[3]), \
          "r"((b)[0]), "r"((b)[1]))

#define LDSM_X4(r, addr) \
    asm volatile("ldmatrix.sync.aligned.m8n8.x4.shared.b16 {%0,%1,%2,%3}, [%4];" \
        : "=r"((r)[0]), "=r"((r)[1]), "=r"((r)[2]), "=r"((r)[3]) : "r"(addr))

// Row pitch 136 bf16 = 272 B (17x16B, conflict-free ldmatrix).
#define PITCHB  272
#define SPLIT_S 34816   // [128 rows][PITCHB] split plane

__device__ __forceinline__ void split_store(char* hi_p, char* lo_p, float2 x) {
    __nv_bfloat162 hi2 = __floats2bfloat162_rn(x.x, x.y);
    float r0 = x.x - __bfloat162float(hi2.x);
    float r1 = x.y - __bfloat162float(hi2.y);
    __nv_bfloat162 lo2 = __floats2bfloat162_rn(r0, r1);
    *(uint32_t*)hi_p = *(uint32_t*)&hi2;
    *(uint32_t*)lo_p = *(uint32_t*)&lo2;
}

// ---------------- SMEM layouts ----------------
// edge kernel (R9 staging, fused epilogue)
#define SM_WB   0
#define SM_WB_S 69632
#define SM_WB_P 34816
#define SM_A    139264
#define SM_A_S  34816
#define SM_PART 208896      // [4 wn][128][8] f32; bank 0 reused as s_ex
#define SM_QI   225280
#define SM_KI   225792
#define SM_EDGE_TOTAL 226304
// proj/out kernels
#define OM_W0   0
#define OM_W1   69632
#define OM_A    139264
#define OM_TOTAL 208896

// ---------------------------------------------------------------------------
// 128x128x128 split-3 MMA core (proj/out)
// ---------------------------------------------------------------------------
__device__ __forceinline__ void mma_tile_128(
    float acc[2][4][4], uint32_t a_base, uint32_t b_base)
{
#pragma unroll
    for (int mt = 0; mt < 2; mt++)
#pragma unroll
        for (int nt = 0; nt < 4; nt++)
#pragma unroll
            for (int el = 0; el < 4; el++) acc[mt][nt][el] = 0.f;

#pragma unroll 2
    for (int ks = 0; ks < 8; ks++) {
        uint32_t bh[4][2], bl[4][2], ah[2][4], al[2][4];
        uint32_t bk = b_base + (uint32_t)ks * 32;
#pragma unroll
        for (int u2 = 0; u2 < 2; u2++) {
            uint32_t tmp[4];
            LDSM_X4(tmp, bk + (uint32_t)(u2 * 16) * PITCHB);
            bh[2*u2][0] = tmp[0]; bh[2*u2][1] = tmp[1];
            bh[2*u2+1][0] = tmp[2]; bh[2*u2+1][1] = tmp[3];
            LDSM_X4(tmp, bk + SPLIT_S + (uint32_t)(u2 * 16) * PITCHB);
            bl[2*u2][0] = tmp[0]; bl[2*u2][1] = tmp[1];
            bl[2*u2+1][0] = tmp[2]; bl[2*u2+1][1] = tmp[3];
        }
        uint32_t ak_ = a_base + (uint32_t)ks * 32;
#pragma unroll
        for (int mt = 0; mt < 2; mt++) {
            LDSM_X4(ah[mt], ak_ + (uint32_t)(mt * 16) * PITCHB);
            LDSM_X4(al[mt], ak_ + SPLIT_S + (uint32_t)(mt * 16) * PITCHB);
        }
#pragma unroll
        for (int mt = 0; mt < 2; mt++)
#pragma unroll
            for (int nt = 0; nt < 4; nt++) {
                MMA_BF16(acc[mt][nt], ah[mt], bh[nt]);
                MMA_BF16(acc[mt][nt], ah[mt], bl[nt]);
                MMA_BF16(acc[mt][nt], al[mt], bh[nt]);
            }
    }
}

__device__ __forceinline__ void store_acc_128(
    float acc[2][4][4], float* outp, int nb,
    int wm, int wn, int g, int t4, int n)
{
#pragma unroll
    for (int mt = 0; mt < 2; mt++)
#pragma unroll
        for (int rh = 0; rh < 2; rh++) {
            int row = nb + wm * 32 + mt * 16 + g + rh * 8;
            if (row < n) {
#pragma unroll
                for (int nt = 0; nt < 4; nt++) {
                    int col = wn * 32 + nt * 8 + t4 * 2;
                    *(float2*)&outp[(size_t)row * HC + col] =
                        make_float2(acc[mt][nt][rh*2], acc[mt][nt][rh*2+1]);
                }
            }
        }
}

// ---------------------------------------------------------------------------
// Init kernels (split so k_edge stays in the profiled 4th slot)
// ---------------------------------------------------------------------------
__global__ void k_init_agg(int n) {
    int i = blockIdx.x * blockDim.x + threadIdx.x;
    if (i < n * HC) g_agg[i] = 0.0f;
}
__global__ void k_init_denom(int n) {
    int i = blockIdx.x * blockDim.x + threadIdx.x;
    if (i < n * NH) g_denom[i] = 0.0f;
}

// ---------------------------------------------------------------------------
// Projections, weights-resident (validated)
// ---------------------------------------------------------------------------
__global__ __launch_bounds__(512, 1) void k_proj_mma(
    const float* __restrict__ query, const float* __restrict__ key,
    const float* __restrict__ Wq, const float* __restrict__ Wkv, int n)
{
    extern __shared__ char smem[];
    uint32_t sbase = smem_u32(smem);

    int tid  = threadIdx.x;
    int warp = tid >> 5;
    int lane = tid & 31;
    int wm   = warp >> 2;
    int wn   = warp & 3;
    int g    = lane >> 2;
    int t4   = lane & 3;

    uint32_t aoff = (uint32_t)(((lane & 7) + 8 * ((lane >> 3) & 1)) * PITCHB
                               + ((lane >> 4) & 1) * 16);
    uint32_t boff = (uint32_t)(((lane & 7) + 8 * ((lane >> 4) & 1)) * PITCHB
                               + ((lane >> 3) & 1) * 16);
    uint32_t a_base = sbase + OM_A  + (uint32_t)(wm * 32) * PITCHB + aoff;
    uint32_t b0     = sbase + OM_W0 + (uint32_t)(wn * 32) * PITCHB + boff;
    uint32_t b1     = sbase + OM_W1 + (uint32_t)(wn * 32) * PITCHB + boff;

    int ntiles = (n + TM - 1) / TM;
    float acc[2][4][4];

    // pass 1: Wq resident
    for (int i = tid; i < 128 * 64; i += 512) {
        int nc = i >> 6, kp = i & 63;
        float2 w = make_float2(Wq[(2 * kp)     * HC + nc],
                               Wq[(2 * kp + 1) * HC + nc]);
        size_t off = (size_t)nc * PITCHB + (size_t)kp * 4;
        split_store(smem + OM_W0 + off, smem + OM_W0 + SPLIT_S + off, w);
    }
    for (int tile = blockIdx.x; tile < ntiles; tile += gridDim.x) {
        int nb = tile * TM;
        __syncthreads();
        for (int i = tid; i < TM * 64; i += 512) {
            int r = i >> 6, cp = i & 63;
            int row = nb + r;
            float2 x = (row < n) ? ((const float2*)query)[(size_t)row * 64 + cp]
                                 : make_float2(0.f, 0.f);
            size_t off = (size_t)r * PITCHB + (size_t)cp * 4;
            split_store(smem + OM_A + off, smem + OM_A + SPLIT_S + off, x);
        }
        __syncthreads();
        mma_tile_128(acc, a_base, b0);
        store_acc_128(acc, g_q, nb, wm, wn, g, t4, n);
    }

    // pass 2: Wk + Wv resident, key staged once
    __syncthreads();
    for (int i = tid; i < 128 * 64; i += 512) {
        int nc = i >> 6, kp = i & 63;
        float2 wk = make_float2(Wkv[(2 * kp)     * COLS + nc],
                                Wkv[(2 * kp + 1) * COLS + nc]);
        float2 wv = make_float2(Wkv[(2 * kp)     * COLS + HC + nc],
                                Wkv[(2 * kp + 1) * COLS + HC + nc]);
        size_t off = (size_t)nc * PITCHB + (size_t)kp * 4;
        split_store(smem + OM_W0 + off, smem + OM_W0 + SPLIT_S + off, wk);
        split_store(smem + OM_W1 + off, smem + OM_W1 + SPLIT_S + off, wv);
    }
    for (int tile = blockIdx.x; tile < ntiles; tile += gridDim.x) {
        int nb = tile * TM;
        __syncthreads();
        for (int i = tid; i < TM * 64; i += 512) {
            int r = i >> 6, cp = i & 63;
            int row = nb + r;
            float2 x = (row < n) ? ((const float2*)key)[(size_t)row * 64 + cp]
                                 : make_float2(0.f, 0.f);
            size_t off = (size_t)r * PITCHB + (size_t)cp * 4;
            split_store(smem + OM_A + off, smem + OM_A + SPLIT_S + off, x);
        }
        __syncthreads();
        mma_tile_128(acc, a_base, b0);
        store_acc_128(acc, g_k, nb, wm, wn, g, t4, n);
        mma_tile_128(acc, a_base, b1);
        store_acc_128(acc, g_v, nb, wm, wn, g, t4, n);
    }
}

// ---------------------------------------------------------------------------
// Edge kernel: bf16 split-3 GEMM + bias-modulated logits + FUSED exp/denom
// and unnormalized scatter (agg += exp(logit) * v). No segment-max: logits
// are bounded (|lg| ~< 35), exp stays well inside fp32; softmax is
// shift-invariant so the final attn ratio is unchanged.
// ---------------------------------------------------------------------------
__global__ __launch_bounds__(512, 1) void k_edge_mma(
    const float* __restrict__ paired, const float* __restrict__ Wb,
    const int* __restrict__ qidx, const int* __restrict__ kidx,
    float* __restrict__ out_logit, int m)
{
    extern __shared__ char smem[];
    uint32_t sbase = smem_u32(smem);

    int tid  = threadIdx.x;
    int warp = tid >> 5;
    int lane = tid & 31;
    int wm   = warp >> 2;
    int wn   = warp & 3;
    int g    = lane >> 2;
    int t4   = lane & 3;

    int*   s_qi   = (int*)(smem + SM_QI);
    int*   s_ki   = (int*)(smem + SM_KI);
    float* s_part = (float*)(smem + SM_PART);   // bank 0 reused as s_ex

    for (int i = tid; i < 2 * 128 * 64; i += 512) {
        int kp = i & 63;
        int nc = (i >> 6) & 127;
        int p  = i >> 13;
        int wn_ = nc >> 5, ln = nc & 31;
        int u = ln >> 4, bias = (ln >> 3) & 1, off = ln & 7;
        int ch   = p * 64 + wn_ * 16 + u * 8 + off;
        int wcol = bias * 128 + ch;
        float2 w = make_float2(Wb[(2 * kp)     * COLS + wcol],
                               Wb[(2 * kp + 1) * COLS + wcol]);
        size_t off_b = (size_t)p * SM_WB_P + (size_t)nc * PITCHB + (size_t)kp * 4;
        split_store(smem + SM_WB + off_b, smem + SM_WB + SM_WB_S + off_b, w);
    }

    uint32_t aoff = (uint32_t)(((lane & 7) + 8 * ((lane >> 3) & 1)) * PITCHB
                               + ((lane >> 4) & 1) * 16);
    uint32_t boff = (uint32_t)(((lane & 7) + 8 * ((lane >> 4) & 1)) * PITCHB
                               + ((lane >> 3) & 1) * 16);
    uint32_t a_base = sbase + SM_A  + (uint32_t)(wm * 32) * PITCHB + aoff;
    uint32_t b_base = sbase + SM_WB + (uint32_t)(wn * 32) * PITCHB + boff;

    int ntiles = (m + TE - 1) / TE;
    for (int tile = blockIdx.x; tile < ntiles; tile += gridDim.x) {
        int ebase = tile * TE;
        __syncthreads();

        for (int i = tid; i < TE * 64; i += 512) {
            int r = i >> 6, cp = i & 63;
            int e = ebase + r;
            float2 x = (e < m) ? ((const float2*)paired)[(size_t)e * 64 + cp]
                               : make_float2(0.f, 0.f);
            size_t off_a = (size_t)r * PITCHB + (size_t)cp * 4;
            split_store(smem + SM_A + off_a, smem + SM_A + SM_A_S + off_a, x);
        }
        if (tid < TE) {
            int e = ebase + tid;
            s_qi[tid] = (e < m) ? qidx[e] : 0;
            s_ki[tid] = (e < m) ? kidx[e] : 0;
        }
        __syncthreads();

        float part[4][2];
#pragma unroll
        for (int a = 0; a < 4; a++) { part[a][0] = 0.f; part[a][1] = 0.f; }

#pragma unroll
        for (int p = 0; p < 2; p++) {
            float acc[2][4][4];
#pragma unroll
            for (int mt = 0; mt < 2; mt++)
#pragma unroll
                for (int nt = 0; nt < 4; nt++)
#pragma unroll
                    for (int el = 0; el < 4; el++) acc[mt][nt][el] = 0.f;

#pragma unroll 2
            for (int ks = 0; ks < 8; ks++) {
                uint32_t bh[4][2], bl[4][2], ah[2][4], al[2][4];
                uint32_t bk = b_base + (uint32_t)p * SM_WB_P + (uint32_t)ks * 32;
#pragma unroll
                for (int u2 = 0; u2 < 2; u2++) {
                    uint32_t tmp[4];
                    LDSM_X4(tmp, bk + (uint32_t)(u2 * 16) * PITCHB);
                    bh[2*u2][0] = tmp[0]; bh[2*u2][1] = tmp[1];
                    bh[2*u2+1][0] = tmp[2]; bh[2*u2+1][1] = tmp[3];
                    LDSM_X4(tmp, bk + SM_WB_S + (uint32_t)(u2 * 16) * PITCHB);
                    bl[2*u2][0] = tmp[0]; bl[2*u2][1] = tmp[1];
                    bl[2*u2+1][0] = tmp[2]; bl[2*u2+1][1] = tmp[3];
                }
                uint32_t ak_ = a_base + (uint32_t)ks * 32;
#pragma unroll
                for (int mt = 0; mt < 2; mt++) {
                    LDSM_X4(ah[mt], ak_ + (uint32_t)(mt * 16) * PITCHB);
                    LDSM_X4(al[mt], ak_ + SM_A_S + (uint32_t)(mt * 16) * PITCHB);
                }
#pragma unroll
                for (int mt = 0; mt < 2; mt++)
#pragma unroll
                    for (int nt = 0; nt < 4; nt++) {
                        MMA_BF16(acc[mt][nt], ah[mt], bh[nt]);
                        MMA_BF16(acc[mt][nt], ah[mt], bl[nt]);
                        MMA_BF16(acc[mt][nt], al[mt], bh[nt]);
                    }
            }

#pragma unroll
            for (int mt = 0; mt < 2; mt++)
#pragma unroll
                for (int rh = 0; rh < 2; rh++) {
                    int eli = wm * 32 + mt * 16 + g + rh * 8;
                    const float* qrow = g_q + (size_t)s_qi[eli] * HC;
                    const float* krow = g_k + (size_t)s_ki[eli] * HC;
#pragma unroll
                    for (int u = 0; u < 2; u++) {
                        int c = p * 64 + wn * 16 + u * 8 + t4 * 2;
                        float2 q2 = *(const float2*)(qrow + c);
                        float2 k2 = *(const float2*)(krow + c);
                        float bm0 = acc[mt][2*u][rh*2],   bm1 = acc[mt][2*u][rh*2+1];
                        float ba0 = acc[mt][2*u+1][rh*2], ba1 = acc[mt][2*u+1][rh*2+1];
                        float qk0 = q2.x * k2.x;
                        float qk1 = q2.y * k2.y;
                        part[mt*2+rh][0] += fmaf(qk0, bm0, qk0) + q2.x * ba0;
                        part[mt*2+rh][1] += fmaf(qk1, bm1, qk1) + q2.y * ba1;
                    }
                }
        }

#pragma unroll
        for (int mt = 0; mt < 2; mt++)
#pragma unroll
            for (int rh = 0; rh < 2; rh++) {
                int eli = wm * 32 + mt * 16 + g + rh * 8;
                float2* sp = (float2*)&s_part[wn * 1024 + eli * 8 + t4 * 2];
                *sp = make_float2(part[mt*2+rh][0], part[mt*2+rh][1]);
            }
        __syncthreads();

        // --- combine, emit logit, exp + denom; s_part bank 0 becomes s_ex ---
#pragma unroll
        for (int j = 0; j < 2; j++) {
            int i  = tid + j * 512;           // 0..1023 = el*8 + h
            int el = i >> 3, h = i & 7;
            int e  = ebase + el;
            float ex = 0.0f;
            if (e < m) {
                float lg = (s_part[i] + s_part[1024 + i])
                         + (s_part[2048 + i] + s_part[3072 + i]);
                out_logit[e * NH + h] = lg;
                ex = expf(lg);
                atomicAdd(&g_denom[s_qi[el] * NH + h], ex);
            }
            s_part[i] = ex;                   // in-place: only this thread reads s_part[i]
        }
        __syncthreads();

        // --- fused unnormalized scatter: agg[qi] += ex * v[ki] ---
        // warp handles one edge per iteration: full 512B v row coalesced.
#pragma unroll
        for (int w = 0; w < 8; w++) {
            int item = tid + w * 512;         // 0..4095
            int el   = item >> 5;             // 0..127
            int cq   = (item & 31) << 2;      // channel base 0,4,..,124
            int e    = ebase + el;
            if (e < m) {
                int ki = s_ki[el], qi = s_qi[el];
                float4 v   = *(const float4*)&g_v[(size_t)ki * HC + cq];
                float4 ex4 = *(const float4*)&s_part[el * 8 + (cq & 4)];
                atomicAdd((float4*)&g_agg[(size_t)qi * HC + cq],
                          make_float4(ex4.x * v.x, ex4.y * v.y,
                                      ex4.z * v.z, ex4.w * v.w));
            }
        }
    }
}

// ---------------------------------------------------------------------------
// result = (agg / denom) @ Wo, weights-resident; /denom fused into staging.
// denom==0 (empty node) -> agg==0 -> emit 0.
// ---------------------------------------------------------------------------
__global__ __launch_bounds__(512, 1) void k_out_mma(
    const float* __restrict__ Wo, float* __restrict__ out, int n)
{
    extern __shared__ char smem[];
    uint32_t sbase = smem_u32(smem);

    int tid  = threadIdx.x;
    int warp = tid >> 5;
    int lane = tid & 31;
    int wm   = warp >> 2;
    int wn   = warp & 3;
    int g    = lane >> 2;
    int t4   = lane & 3;

    uint32_t aoff = (uint32_t)(((lane & 7) + 8 * ((lane >> 3) & 1)) * PITCHB
                               + ((lane >> 4) & 1) * 16);
    uint32_t boff = (uint32_t)(((lane & 7) + 8 * ((lane >> 4) & 1)) * PITCHB
                               + ((lane >> 3) & 1) * 16);
    uint32_t a_base = sbase + OM_A  + (uint32_t)(wm * 32) * PITCHB + aoff;
    uint32_t b0     = sbase + OM_W0 + (uint32_t)(wn * 32) * PITCHB + boff;

    for (int i = tid; i < 128 * 64; i += 512) {
        int nc = i >> 6, kp = i & 63;
        float2 w = make_float2(Wo[(2 * kp)     * HC + nc],
                               Wo[(2 * kp + 1) * HC + nc]);
        size_t off = (size_t)nc * PITCHB + (size_t)kp * 4;
        split_store(smem + OM_W0 + off, smem + OM_W0 + SPLIT_S + off, w);
    }

    int ntiles = (n + TM - 1) / TM;
    float acc[2][4][4];
    for (int tile = blockIdx.x; tile < ntiles; tile += gridDim.x) {
        int nb = tile * TM;
        __syncthreads();
        for (int i = tid; i < TM * 64; i += 512) {
            int r = i >> 6, cp = i & 63;
            int row = nb + r;
            float2 x = make_float2(0.f, 0.f);
            if (row < n) {
                x = ((const float2*)g_agg)[(size_t)row * 64 + cp];
                int c0 = (2 * cp) & 7;
                float2 dn = *(const float2*)&g_denom[(size_t)row * NH + c0];
                x.x = (dn.x != 0.0f) ? x.x / dn.x : 0.0f;
                x.y = (dn.y != 0.0f) ? x.y / dn.y : 0.0f;
            }
            size_t off = (size_t)r * PITCHB + (size_t)cp * 4;
            split_store(smem + OM_A + off, smem + OM_A + SPLIT_S + off, x);
        }
        __syncthreads();
        mma_tile_128(acc, a_base, b0);
        store_acc_128(acc, out, nb, wm, wn, g, t4, n);
    }
}

// ---------------------------------------------------------------------------
extern "C" void kernel_launch(void* const* d_in, const int* in_sizes, int n_in,
                              void* d_out, int out_size)
{
    const float* query  = (const float*)d_in[0];
    const float* key    = (const float*)d_in[1];
    const int*   qidx   = (const int*)  d_in[2];
    const int*   kidx   = (const int*)  d_in[3];
    const float* paired = (const float*)d_in[4];
    const float* Wq     = (const float*)d_in[5];
    const float* Wkv    = (const float*)d_in[6];
    const float* Wb     = (const float*)d_in[7];
    const float* Wo     = (const float*)d_in[8];

    int n = in_sizes[0] / HC;   // 50000
    int m = in_sizes[2];        // 400000

    float* out_result = (float*)d_out;           // n*HC
    float* out_logit  = (float*)d_out + n * HC;  // m*NH

    cudaFuncSetAttribute(k_edge_mma, cudaFuncAttributeMaxDynamicSharedMemorySize,
                         SM_EDGE_TOTAL);
    cudaFuncSetAttribute(k_proj_mma, cudaFuncAttributeMaxDynamicSharedMemorySize,
                         OM_TOTAL);
    cudaFuncSetAttribute(k_out_mma, cudaFuncAttributeMaxDynamicSharedMemorySize,
                         OM_TOTAL);

    int dev = 0, nsm = 148;
    cudaGetDevice(&dev);
    cudaDeviceGetAttribute(&nsm, cudaDevAttrMultiProcessorCount, dev);

    int etiles = (m + TE - 1) / TE;
    int egrid  = etiles < nsm ? etiles : nsm;
    int ptiles = (n + TM - 1) / TM;
    int pgrid  = ptiles < nsm ? ptiles : nsm;

    // k_edge_mma stays the 4th launch (profiled slot).
    k_init_agg<<<(n * HC + 255) / 256, 256>>>(n);                        // 1
    k_proj_mma<<<pgrid, 512, OM_TOTAL>>>(query, key, Wq, Wkv, n);        // 2
    k_init_denom<<<(n * NH + 255) / 256, 256>>>(n);                      // 3
    k_edge_mma<<<egrid, 512, SM_EDGE_TOTAL>>>(paired, Wb, qidx, kidx,    // 4
                                              out_logit, m);
    k_out_mma<<<pgrid, 512, OM_TOTAL>>>(Wo, out_result, n);              // 5
}

// round 15
// speedup vs baseline: 1.0629x; 1.0629x over previous
#include <cuda_runtime.h>
#include <cuda_bf16.h>
#include <math.h>
#include <stdint.h>

#define HC   128
#define NH   8
#define COLS 256
#define MAXN 50000
#define MAXM 400000
#define TM   128   // rows per tile (proj/out)
#define TE   128   // edges per tile (edge kernel)

typedef unsigned long long ull;

// Scratch (device globals — no allocation allowed)
__device__ float g_q[MAXN * HC];
__device__ float g_k[MAXN * HC];
__device__ float g_v[MAXN * HC];
__device__ float g_agg[MAXN * HC];
__device__ float g_denom[MAXN * NH];
__device__ float g_ex[MAXM * NH];

__device__ __forceinline__ uint32_t smem_u32(const void* p) {
    uint32_t a;
    asm("{ .reg .u64 t; cvta.to.shared.u64 t, %1; cvt.u32.u64 %0, t; }"
        : "=r"(a) : "l"(p));
    return a;
}

// ---------------------------------------------------------------------------
// mma.sync / ldmatrix (base PTX ISA — valid for compute_103)
// ---------------------------------------------------------------------------
#define MMA_BF16(c, a, b) \
    asm volatile( \
        "mma.sync.aligned.m16n8k16.row.col.f32.bf16.bf16.f32 " \
        "{%0,%1,%2,%3}, {%4,%5,%6,%7}, {%8,%9}, {%0,%1,%2,%3};" \
        : "+f"((c)[0]), "+f"((c)[1]), "+f"((c)[2]), "+f"((c)[3]) \
        : "r"((a)[0]), "r"((a)[1]), "r"((a)[2]), "r"((a)[3]), \
          "r"((b)[0]), "r"((b)[1]))

#define LDSM_X4(r, addr) \
    asm volatile("ldmatrix.sync.aligned.m8n8.x4.shared.b16 {%0,%1,%2,%3}, [%4];" \
        : "=r"((r)[0]), "=r"((r)[1]), "=r"((r)[2]), "=r"((r)[3]) : "r"(addr))

// Row pitch 136 bf16 = 272 B (17x16B, conflict-free ldmatrix).
#define PITCHB  272
#define SPLIT_S 34816   // [128 rows][PITCHB] split plane

__device__ __forceinline__ void split_store(char* hi_p, char* lo_p, float2 x) {
    __nv_bfloat162 hi2 = __floats2bfloat162_rn(x.x, x.y);
    float r0 = x.x - __bfloat162float(hi2.x);
    float r1 = x.y - __bfloat162float(hi2.y);
    __nv_bfloat162 lo2 = __floats2bfloat162_rn(r0, r1);
    *(uint32_t*)hi_p = *(uint32_t*)&hi2;
    *(uint32_t*)lo_p = *(uint32_t*)&lo2;
}

// ---------------- SMEM layouts ----------------
// edge kernel (R9-validated staging)
#define SM_WB   0
#define SM_WB_S 69632
#define SM_WB_P 34816
#define SM_A    139264
#define SM_A_S  34816
#define SM_PART 208896
#define SM_QI   225280
#define SM_KI   225792
#define SM_EDGE_TOTAL 226304
// proj/out kernels
#define OM_W0   0
#define OM_W1   69632
#define OM_A    139264
#define OM_TOTAL 208896

// ---------------------------------------------------------------------------
// 128x128x128 split-3 MMA core (proj/out)
// ---------------------------------------------------------------------------
__device__ __forceinline__ void mma_tile_128(
    float acc[2][4][4], uint32_t a_base, uint32_t b_base)
{
#pragma unroll
    for (int mt = 0; mt < 2; mt++)
#pragma unroll
        for (int nt = 0; nt < 4; nt++)
#pragma unroll
            for (int el = 0; el < 4; el++) acc[mt][nt][el] = 0.f;

#pragma unroll 2
    for (int ks = 0; ks < 8; ks++) {
        uint32_t bh[4][2], bl[4][2], ah[2][4], al[2][4];
        uint32_t bk = b_base + (uint32_t)ks * 32;
#pragma unroll
        for (int u2 = 0; u2 < 2; u2++) {
            uint32_t tmp[4];
            LDSM_X4(tmp, bk + (uint32_t)(u2 * 16) * PITCHB);
            bh[2*u2][0] = tmp[0]; bh[2*u2][1] = tmp[1];
            bh[2*u2+1][0] = tmp[2]; bh[2*u2+1][1] = tmp[3];
            LDSM_X4(tmp, bk + SPLIT_S + (uint32_t)(u2 * 16) * PITCHB);
            bl[2*u2][0] = tmp[0]; bl[2*u2][1] = tmp[1];
            bl[2*u2+1][0] = tmp[2]; bl[2*u2+1][1] = tmp[3];
        }
        uint32_t ak_ = a_base + (uint32_t)ks * 32;
#pragma unroll
        for (int mt = 0; mt < 2; mt++) {
            LDSM_X4(ah[mt], ak_ + (uint32_t)(mt * 16) * PITCHB);
            LDSM_X4(al[mt], ak_ + SPLIT_S + (uint32_t)(mt * 16) * PITCHB);
        }
#pragma unroll
        for (int mt = 0; mt < 2; mt++)
#pragma unroll
            for (int nt = 0; nt < 4; nt++) {
                MMA_BF16(acc[mt][nt], ah[mt], bh[nt]);
                MMA_BF16(acc[mt][nt], ah[mt], bl[nt]);
                MMA_BF16(acc[mt][nt], al[mt], bh[nt]);
            }
    }
}

__device__ __forceinline__ void store_acc_128(
    float acc[2][4][4], float* outp, int nb,
    int wm, int wn, int g, int t4, int n)
{
#pragma unroll
    for (int mt = 0; mt < 2; mt++)
#pragma unroll
        for (int rh = 0; rh < 2; rh++) {
            int row = nb + wm * 32 + mt * 16 + g + rh * 8;
            if (row < n) {
#pragma unroll
                for (int nt = 0; nt < 4; nt++) {
                    int col = wn * 32 + nt * 8 + t4 * 2;
                    *(float2*)&outp[(size_t)row * HC + col] =
                        make_float2(acc[mt][nt][rh*2], acc[mt][nt][rh*2+1]);
                }
            }
        }
}

// ---------------------------------------------------------------------------
// Init kernels (split so k_edge stays in the profiled 4th slot)
// ---------------------------------------------------------------------------
__global__ void k_init_agg(int n) {
    int i = blockIdx.x * blockDim.x + threadIdx.x;
    if (i < n * HC) g_agg[i] = 0.0f;
}
__global__ void k_init_denom(int n) {
    int i = blockIdx.x * blockDim.x + threadIdx.x;
    if (i < n * NH) g_denom[i] = 0.0f;
}

// ---------------------------------------------------------------------------
// Projections, weights-resident (validated)
// ---------------------------------------------------------------------------
__global__ __launch_bounds__(512, 1) void k_proj_mma(
    const float* __restrict__ query, const float* __restrict__ key,
    const float* __restrict__ Wq, const float* __restrict__ Wkv, int n)
{
    extern __shared__ char smem[];
    uint32_t sbase = smem_u32(smem);

    int tid  = threadIdx.x;
    int warp = tid >> 5;
    int lane = tid & 31;
    int wm   = warp >> 2;
    int wn   = warp & 3;
    int g    = lane >> 2;
    int t4   = lane & 3;

    uint32_t aoff = (uint32_t)(((lane & 7) + 8 * ((lane >> 3) & 1)) * PITCHB
                               + ((lane >> 4) & 1) * 16);
    uint32_t boff = (uint32_t)(((lane & 7) + 8 * ((lane >> 4) & 1)) * PITCHB
                               + ((lane >> 3) & 1) * 16);
    uint32_t a_base = sbase + OM_A  + (uint32_t)(wm * 32) * PITCHB + aoff;
    uint32_t b0     = sbase + OM_W0 + (uint32_t)(wn * 32) * PITCHB + boff;
    uint32_t b1     = sbase + OM_W1 + (uint32_t)(wn * 32) * PITCHB + boff;

    int ntiles = (n + TM - 1) / TM;
    float acc[2][4][4];

    // pass 1: Wq resident
    for (int i = tid; i < 128 * 64; i += 512) {
        int nc = i >> 6, kp = i & 63;
        float2 w = make_float2(Wq[(2 * kp)     * HC + nc],
                               Wq[(2 * kp + 1) * HC + nc]);
        size_t off = (size_t)nc * PITCHB + (size_t)kp * 4;
        split_store(smem + OM_W0 + off, smem + OM_W0 + SPLIT_S + off, w);
    }
    for (int tile = blockIdx.x; tile < ntiles; tile += gridDim.x) {
        int nb = tile * TM;
        __syncthreads();
        for (int i = tid; i < TM * 64; i += 512) {
            int r = i >> 6, cp = i & 63;
            int row = nb + r;
            float2 x = (row < n) ? ((const float2*)query)[(size_t)row * 64 + cp]
                                 : make_float2(0.f, 0.f);
            size_t off = (size_t)r * PITCHB + (size_t)cp * 4;
            split_store(smem + OM_A + off, smem + OM_A + SPLIT_S + off, x);
        }
        __syncthreads();
        mma_tile_128(acc, a_base, b0);
        store_acc_128(acc, g_q, nb, wm, wn, g, t4, n);
    }

    // pass 2: Wk + Wv resident, key staged once
    __syncthreads();
    for (int i = tid; i < 128 * 64; i += 512) {
        int nc = i >> 6, kp = i & 63;
        float2 wk = make_float2(Wkv[(2 * kp)     * COLS + nc],
                                Wkv[(2 * kp + 1) * COLS + nc]);
        float2 wv = make_float2(Wkv[(2 * kp)     * COLS + HC + nc],
                                Wkv[(2 * kp + 1) * COLS + HC + nc]);
        size_t off = (size_t)nc * PITCHB + (size_t)kp * 4;
        split_store(smem + OM_W0 + off, smem + OM_W0 + SPLIT_S + off, wk);
        split_store(smem + OM_W1 + off, smem + OM_W1 + SPLIT_S + off, wv);
    }
    for (int tile = blockIdx.x; tile < ntiles; tile += gridDim.x) {
        int nb = tile * TM;
        __syncthreads();
        for (int i = tid; i < TM * 64; i += 512) {
            int r = i >> 6, cp = i & 63;
            int row = nb + r;
            float2 x = (row < n) ? ((const float2*)key)[(size_t)row * 64 + cp]
                                 : make_float2(0.f, 0.f);
            size_t off = (size_t)r * PITCHB + (size_t)cp * 4;
            split_store(smem + OM_A + off, smem + OM_A + SPLIT_S + off, x);
        }
        __syncthreads();
        mma_tile_128(acc, a_base, b0);
        store_acc_128(acc, g_k, nb, wm, wn, g, t4, n);
        mma_tile_128(acc, a_base, b1);
        store_acc_128(acc, g_v, nb, wm, wn, g, t4, n);
    }
}

// ---------------------------------------------------------------------------
// Edge kernel: R9-validated GEMM/staging. Epilogue fuses exp + denom accum
// (no segment-max: logits bounded; softmax shift-invariant — R14-validated).
// ---------------------------------------------------------------------------
__global__ __launch_bounds__(512, 1) void k_edge_mma(
    const float* __restrict__ paired, const float* __restrict__ Wb,
    const int* __restrict__ qidx, const int* __restrict__ kidx,
    float* __restrict__ out_logit, int m)
{
    extern __shared__ char smem[];
    uint32_t sbase = smem_u32(smem);

    int tid  = threadIdx.x;
    int warp = tid >> 5;
    int lane = tid & 31;
    int wm   = warp >> 2;
    int wn   = warp & 3;
    int g    = lane >> 2;
    int t4   = lane & 3;

    int*   s_qi   = (int*)(smem + SM_QI);
    int*   s_ki   = (int*)(smem + SM_KI);
    float* s_part = (float*)(smem + SM_PART);

    for (int i = tid; i < 2 * 128 * 64; i += 512) {
        int kp = i & 63;
        int nc = (i >> 6) & 127;
        int p  = i >> 13;
        int wn_ = nc >> 5, ln = nc & 31;
        int u = ln >> 4, bias = (ln >> 3) & 1, off = ln & 7;
        int ch   = p * 64 + wn_ * 16 + u * 8 + off;
        int wcol = bias * 128 + ch;
        float2 w = make_float2(Wb[(2 * kp)     * COLS + wcol],
                               Wb[(2 * kp + 1) * COLS + wcol]);
        size_t off_b = (size_t)p * SM_WB_P + (size_t)nc * PITCHB + (size_t)kp * 4;
        split_store(smem + SM_WB + off_b, smem + SM_WB + SM_WB_S + off_b, w);
    }

    uint32_t aoff = (uint32_t)(((lane & 7) + 8 * ((lane >> 3) & 1)) * PITCHB
                               + ((lane >> 4) & 1) * 16);
    uint32_t boff = (uint32_t)(((lane & 7) + 8 * ((lane >> 4) & 1)) * PITCHB
                               + ((lane >> 3) & 1) * 16);
    uint32_t a_base = sbase + SM_A  + (uint32_t)(wm * 32) * PITCHB + aoff;
    uint32_t b_base = sbase + SM_WB + (uint32_t)(wn * 32) * PITCHB + boff;

    int ntiles = (m + TE - 1) / TE;
    for (int tile = blockIdx.x; tile < ntiles; tile += gridDim.x) {
        int ebase = tile * TE;
        __syncthreads();

        for (int i = tid; i < TE * 64; i += 512) {
            int r = i >> 6, cp = i & 63;
            int e = ebase + r;
            float2 x = (e < m) ? ((const float2*)paired)[(size_t)e * 64 + cp]
                               : make_float2(0.f, 0.f);
            size_t off_a = (size_t)r * PITCHB + (size_t)cp * 4;
            split_store(smem + SM_A + off_a, smem + SM_A + SM_A_S + off_a, x);
        }
        if (tid < TE) {
            int e = ebase + tid;
            s_qi[tid] = (e < m) ? qidx[e] : 0;
            s_ki[tid] = (e < m) ? kidx[e] : 0;
        }
        __syncthreads();

        float part[4][2];
#pragma unroll
        for (int a = 0; a < 4; a++) { part[a][0] = 0.f; part[a][1] = 0.f; }

#pragma unroll
        for (int p = 0; p < 2; p++) {
            float acc[2][4][4];
#pragma unroll
            for (int mt = 0; mt < 2; mt++)
#pragma unroll
                for (int nt = 0; nt < 4; nt++)
#pragma unroll
                    for (int el = 0; el < 4; el++) acc[mt][nt][el] = 0.f;

#pragma unroll 2
            for (int ks = 0; ks < 8; ks++) {
                uint32_t bh[4][2], bl[4][2], ah[2][4], al[2][4];
                uint32_t bk = b_base + (uint32_t)p * SM_WB_P + (uint32_t)ks * 32;
#pragma unroll
                for (int u2 = 0; u2 < 2; u2++) {
                    uint32_t tmp[4];
                    LDSM_X4(tmp, bk + (uint32_t)(u2 * 16) * PITCHB);
                    bh[2*u2][0] = tmp[0]; bh[2*u2][1] = tmp[1];
                    bh[2*u2+1][0] = tmp[2]; bh[2*u2+1][1] = tmp[3];
                    LDSM_X4(tmp, bk + SM_WB_S + (uint32_t)(u2 * 16) * PITCHB);
                    bl[2*u2][0] = tmp[0]; bl[2*u2][1] = tmp[1];
                    bl[2*u2+1][0] = tmp[2]; bl[2*u2+1][1] = tmp[3];
                }
                uint32_t ak_ = a_base + (uint32_t)ks * 32;
#pragma unroll
                for (int mt = 0; mt < 2; mt++) {
                    LDSM_X4(ah[mt], ak_ + (uint32_t)(mt * 16) * PITCHB);
                    LDSM_X4(al[mt], ak_ + SM_A_S + (uint32_t)(mt * 16) * PITCHB);
                }
#pragma unroll
                for (int mt = 0; mt < 2; mt++)
#pragma unroll
                    for (int nt = 0; nt < 4; nt++) {
                        MMA_BF16(acc[mt][nt], ah[mt], bh[nt]);
                        MMA_BF16(acc[mt][nt], ah[mt], bl[nt]);
                        MMA_BF16(acc[mt][nt], al[mt], bh[nt]);
                    }
            }

#pragma unroll
            for (int mt = 0; mt < 2; mt++)
#pragma unroll
                for (int rh = 0; rh < 2; rh++) {
                    int eli = wm * 32 + mt * 16 + g + rh * 8;
                    const float* qrow = g_q + (size_t)s_qi[eli] * HC;
                    const float* krow = g_k + (size_t)s_ki[eli] * HC;
#pragma unroll
                    for (int u = 0; u < 2; u++) {
                        int c = p * 64 + wn * 16 + u * 8 + t4 * 2;
                        float2 q2 = *(const float2*)(qrow + c);
                        float2 k2 = *(const float2*)(krow + c);
                        float bm0 = acc[mt][2*u][rh*2],   bm1 = acc[mt][2*u][rh*2+1];
                        float ba0 = acc[mt][2*u+1][rh*2], ba1 = acc[mt][2*u+1][rh*2+1];
                        float qk0 = q2.x * k2.x;
                        float qk1 = q2.y * k2.y;
                        part[mt*2+rh][0] += fmaf(qk0, bm0, qk0) + q2.x * ba0;
                        part[mt*2+rh][1] += fmaf(qk1, bm1, qk1) + q2.y * ba1;
                    }
                }
        }

#pragma unroll
        for (int mt = 0; mt < 2; mt++)
#pragma unroll
            for (int rh = 0; rh < 2; rh++) {
                int eli = wm * 32 + mt * 16 + g + rh * 8;
                float2* sp = (float2*)&s_part[wn * 1024 + eli * 8 + t4 * 2];
                *sp = make_float2(part[mt*2+rh][0], part[mt*2+rh][1]);
            }
        __syncthreads();

        // combine 4 N-groups; emit logit, exp, denom accumulation
#pragma unroll
        for (int j = 0; j < 2; j++) {
            int i  = tid + j * 512;
            int el = i >> 3, h = i & 7;
            int e  = ebase + el;
            if (e < m) {
                float lg = (s_part[i] + s_part[1024 + i])
                         + (s_part[2048 + i] + s_part[3072 + i]);
                out_logit[e * NH + h] = lg;
                float ex = expf(lg);
                g_ex[e * NH + h] = ex;
                atomicAdd(&g_denom[s_qi[el] * NH + h], ex);
            }
        }
    }
}

// ---------------------------------------------------------------------------
// scatter (normalized): agg[qi] += (ex/denom) * v[ki]   (R9-validated, 45us)
// ---------------------------------------------------------------------------
__global__ void k_scatter(const int* __restrict__ qidx,
                          const int* __restrict__ kidx, int m)
{
    int i = blockIdx.x * blockDim.x + threadIdx.x;
    if (i >= m * 32) return;
    int e  = i >> 5;
    int c4 = (i & 31) << 2;
    int qi = qidx[e];
    float4 v  = *(const float4*)&g_v[kidx[e] * HC + c4];
    float4 ex = *(const float4*)&g_ex[(e << 3) + (c4 & 7)];
    float4 dn = *(const float4*)&g_denom[qi * NH + (c4 & 7)];
    float4 val = make_float4((ex.x / dn.x) * v.x, (ex.y / dn.y) * v.y,
                             (ex.z / dn.z) * v.z, (ex.w / dn.w) * v.w);
    atomicAdd((float4*)&g_agg[qi * HC + c4], val);
}

// ---------------------------------------------------------------------------
// result = agg @ Wo, weights-resident (validated)
// ---------------------------------------------------------------------------
__global__ __launch_bounds__(512, 1) void k_out_mma(
    const float* __restrict__ Wo, float* __restrict__ out, int n)
{
    extern __shared__ char smem[];
    uint32_t sbase = smem_u32(smem);

    int tid  = threadIdx.x;
    int warp = tid >> 5;
    int lane = tid & 31;
    int wm   = warp >> 2;
    int wn   = warp & 3;
    int g    = lane >> 2;
    int t4   = lane & 3;

    uint32_t aoff = (uint32_t)(((lane & 7) + 8 * ((lane >> 3) & 1)) * PITCHB
                               + ((lane >> 4) & 1) * 16);
    uint32_t boff = (uint32_t)(((lane & 7) + 8 * ((lane >> 4) & 1)) * PITCHB
                               + ((lane >> 3) & 1) * 16);
    uint32_t a_base = sbase + OM_A  + (uint32_t)(wm * 32) * PITCHB + aoff;
    uint32_t b0     = sbase + OM_W0 + (uint32_t)(wn * 32) * PITCHB + boff;

    for (int i = tid; i < 128 * 64; i += 512) {
        int nc = i >> 6, kp = i & 63;
        float2 w = make_float2(Wo[(2 * kp)     * HC + nc],
                               Wo[(2 * kp + 1) * HC + nc]);
        size_t off = (size_t)nc * PITCHB + (size_t)kp * 4;
        split_store(smem + OM_W0 + off, smem + OM_W0 + SPLIT_S + off, w);
    }

    int ntiles = (n + TM - 1) / TM;
    float acc[2][4][4];
    for (int tile = blockIdx.x; tile < ntiles; tile += gridDim.x) {
        int nb = tile * TM;
        __syncthreads();
        for (int i = tid; i < TM * 64; i += 512) {
            int r = i >> 6, cp = i & 63;
            int row = nb + r;
            float2 x = (row < n) ? ((const float2*)g_agg)[(size_t)row * 64 + cp]
                                 : make_float2(0.f, 0.f);
            size_t off = (size_t)r * PITCHB + (size_t)cp * 4;
            split_store(smem + OM_A + off, smem + OM_A + SPLIT_S + off, x);
        }
        __syncthreads();
        mma_tile_128(acc, a_base, b0);
        store_acc_128(acc, out, nb, wm, wn, g, t4, n);
    }
}

// ---------------------------------------------------------------------------
extern "C" void kernel_launch(void* const* d_in, const int* in_sizes, int n_in,
                              void* d_out, int out_size)
{
    const float* query  = (const float*)d_in[0];
    const float* key    = (const float*)d_in[1];
    const int*   qidx   = (const int*)  d_in[2];
    const int*   kidx   = (const int*)  d_in[3];
    const float* paired = (const float*)d_in[4];
    const float* Wq     = (const float*)d_in[5];
    const float* Wkv    = (const float*)d_in[6];
    const float* Wb     = (const float*)d_in[7];
    const float* Wo     = (const float*)d_in[8];

    int n = in_sizes[0] / HC;   // 50000
    int m = in_sizes[2];        // 400000

    float* out_result = (float*)d_out;           // n*HC
    float* out_logit  = (float*)d_out + n * HC;  // m*NH

    cudaFuncSetAttribute(k_edge_mma, cudaFuncAttributeMaxDynamicSharedMemorySize,
                         SM_EDGE_TOTAL);
    cudaFuncSetAttribute(k_proj_mma, cudaFuncAttributeMaxDynamicSharedMemorySize,
                         OM_TOTAL);
    cudaFuncSetAttribute(k_out_mma, cudaFuncAttributeMaxDynamicSharedMemorySize,
                         OM_TOTAL);

    int dev = 0, nsm = 148;
    cudaGetDevice(&dev);
    cudaDeviceGetAttribute(&nsm, cudaDevAttrMultiProcessorCount, dev);

    int etiles = (m + TE - 1) / TE;
    int egrid  = etiles < nsm ? etiles : nsm;
    int ptiles = (n + TM - 1) / TM;
    int pgrid  = ptiles < nsm ? ptiles : nsm;

    // k_edge_mma stays the 4th launch (profiled slot).
    k_init_agg<<<(n * HC + 255) / 256, 256>>>(n);                        // 1
    k_proj_mma<<<pgrid, 512, OM_TOTAL>>>(query, key, Wq, Wkv, n);        // 2
    k_init_denom<<<(n * NH + 255) / 256, 256>>>(n);                      // 3
    k_edge_mma<<<egrid, 512, SM_EDGE_TOTAL>>>(paired, Wb, qidx, kidx,    // 4
                                              out_logit, m);
    k_scatter<<<(m * 32 + 255) / 256, 256>>>(qidx, kidx, m);             // 5
    k_out_mma<<<pgrid, 512, OM_TOTAL>>>(Wo, out_result, n);              // 6
}